// round 2
// baseline (speedup 1.0000x reference)
#include <cuda_runtime.h>
#include <math.h>
#include <stdint.h>

// Problem constants
#define BB 16
#define NN 4096
#define DD 64
#define OO 12
#define SS 32
#define MM 12
#define AA 32

#define TILE_N 64
#define THREADS 128

#define SCALE 0.17677669529663687f   // 1/sqrt(32)
#define TWO_PI 6.283185307179586f

// Scratch layout per (b,o): key[12][32] | valg[12][64] | cmb[12] | pad[4]
#define KEY_OFF  0
#define VALG_OFF 384
#define CMB_OFF  1152
#define PER_BO   1168                 // floats (16B-aligned chunks)

__device__ float g_scratch[BB * OO * PER_BO];

#define ATTN_OUT_OFF ((size_t)BB*OO*NN*DD)                 // 50331648
#define GATE_OUT_OFF (ATTN_OUT_OFF + (size_t)BB*OO*NN*MM)  // 59768832

// Shared memory (static): Wqt[64][34] | buf[2][PER_BO]
#define WQT_STRIDE 34
#define SM_WQT 0
#define SM_BUF (SM_WQT + DD*WQT_STRIDE)     // 2176
#define SMEM_FLOATS (SM_BUF + 2*PER_BO)     // 4512 floats = 18048 B

// Packed dual-FMA (fp32x2) — ptxas never auto-fuses this (SASS_QUICKREF).
__device__ __forceinline__ float2 ffma2(float2 a, float2 b, float2 c) {
    float2 d;
    asm("{\n"
        ".reg .b64 ra, rb, rc, rd;\n"
        "mov.b64 ra, {%2, %3};\n"
        "mov.b64 rb, {%4, %5};\n"
        "mov.b64 rc, {%6, %7};\n"
        "fma.rn.f32x2 rd, ra, rb, rc;\n"
        "mov.b64 {%0, %1}, rd;\n"
        "}"
        : "=f"(d.x), "=f"(d.y)
        : "f"(a.x), "f"(a.y), "f"(b.x), "f"(b.y), "f"(c.x), "f"(c.y));
    return d;
}

__device__ __forceinline__ void cp_async16(uint32_t dst_smem, const void* src) {
    asm volatile("cp.async.cg.shared.global [%0], [%1], 16;\n"
                 :: "r"(dst_smem), "l"(src));
}
__device__ __forceinline__ void cp_async_commit() {
    asm volatile("cp.async.commit_group;\n");
}
__device__ __forceinline__ void cp_async_wait_all() {
    asm volatile("cp.async.wait_group 0;\n" ::: "memory");
}

// ---------------------------------------------------------------------------
// Precompute per-(b,o) small tensors: key, gate*val_emb, cmb, gate output.
// ---------------------------------------------------------------------------
__global__ void precompute_kernel(const float* __restrict__ ts_out,
                                  const float* __restrict__ step_emb,
                                  const float* __restrict__ key_emb,
                                  const float* __restrict__ val_emb,
                                  const float* __restrict__ Wk,
                                  const float* __restrict__ Wg,
                                  const float* __restrict__ bg,
                                  const float* __restrict__ Wq,
                                  const float* __restrict__ bq,
                                  float* __restrict__ out)
{
    __shared__ float qs_s[AA];
    __shared__ float key_sh[MM * AA];
    __shared__ float gate_sh[MM];

    const int bo = blockIdx.x;
    const int t  = threadIdx.x;
    const float tod = ts_out[bo * 2 + 0];
    const float dow = ts_out[bo * 2 + 1];
    float* dst = g_scratch + (size_t)bo * PER_BO;

    // key[m][a]
    for (int i = t; i < MM * AA; i += 64) {
        int m = i >> 5, a = i & 31;
        float ph = (m < 8) ? tod : dow;
        float kf = (m < 8) ? (float)(m + 1) : (float)(m - 7);
        float sn, cs; sincosf(TWO_PI * ph * kf, &sn, &cs);
        float kv = sn * Wk[a * 2 + 0] + cs * Wk[a * 2 + 1] + key_emb[i];
        dst[KEY_OFF + i] = kv;
        key_sh[i] = kv;
    }
    // gate[m] (+ gate output)
    if (t < MM) {
        int m = t;
        float ph = (m < 8) ? tod : dow;
        float kf = (m < 8) ? (float)(m + 1) : (float)(m - 7);
        float sn, cs; sincosf(TWO_PI * ph * kf, &sn, &cs);
        float gv = tanhf(sn * Wg[0] + cs * Wg[1] + bg[0]);
        gate_sh[m] = gv;
        out[GATE_OUT_OFF + (size_t)bo * MM + m] = gv;
    }
    // qs[a]
    if (t < AA) {
        float acc = bq[t];
        const float* se = step_emb + bo * SS;
        const float* wr = Wq + t * (DD + SS) + DD;
        #pragma unroll 8
        for (int si = 0; si < SS; si++) acc = fmaf(se[si], wr[si], acc);
        qs_s[t] = acc;
    }
    __syncthreads();
    // valg[m][d] = gate[m] * val_emb[m][d]
    for (int i = t; i < MM * DD; i += 64) {
        int m = i >> 6;
        dst[VALG_OFF + i] = gate_sh[m] * val_emb[i];
    }
    // cmb[m] = qs . key[m]
    if (t < MM) {
        float acc = 0.f;
        #pragma unroll
        for (int a = 0; a < AA; a++) acc += qs_s[a] * key_sh[t * AA + a];
        dst[CMB_OFF + t] = acc;
    }
    if (t < 4) dst[CMB_OFF + MM + t] = 0.f;  // pad
}

// ---------------------------------------------------------------------------
// Main kernel: one block = (b, 64-row tile), loops over O. Single wave.
// ---------------------------------------------------------------------------
__global__ __launch_bounds__(THREADS, 7)
void stta_main(const float* __restrict__ H, const float* __restrict__ Wq,
               float* __restrict__ out)
{
    __shared__ float s[SMEM_FLOATS];
    float* Wqt = s + SM_WQT;     // [64][34]  Wqt[d][a]
    float* buf = s + SM_BUF;     // [2][PER_BO]

    const int t  = threadIdx.x;
    const int b  = blockIdx.y;
    const int n0 = blockIdx.x * TILE_N;

    // Stage o=0 params via cp.async
    {
        const float* src = g_scratch + (size_t)(b * OO) * PER_BO;
        uint32_t nb = (uint32_t)__cvta_generic_to_shared(buf);
        for (int i = t; i < PER_BO / 4; i += THREADS)
            cp_async16(nb + (uint32_t)i * 16, src + i * 4);
        cp_async_commit();
    }
    // Stage Wqt[d][a] = Wq[a][d]
    for (int i = t; i < AA * DD; i += THREADS) {
        int a = i >> 6, d = i & 63;
        Wqt[d * WQT_STRIDE + a] = Wq[a * (DD + SS) + d];
    }
    cp_async_wait_all();
    __syncthreads();

    const int r  = t >> 1;     // row in tile
    const int h  = t & 1;      // a/d half
    const int a0 = h * 16;

    // qh[r][a0..a0+16) in registers (H read from global, stays in L1)
    const float* Hrow = H + ((size_t)b * NN + n0 + r) * DD;
    float2 qh2[8];
    #pragma unroll
    for (int j = 0; j < 8; j++) qh2[j] = make_float2(0.f, 0.f);

    #define QH_STEP(HV, DI)                                             \
        {   float2 hd = make_float2((HV), (HV));                        \
            const float* wrow = Wqt + (DI) * WQT_STRIDE + a0;           \
            _Pragma("unroll")                                           \
            for (int j = 0; j < 8; j++)                                 \
                qh2[j] = ffma2(hd, *(const float2*)(wrow + 2 * j), qh2[j]); }

    {
        const float4* Hrow4 = (const float4*)Hrow;
        #pragma unroll 4
        for (int d4 = 0; d4 < 16; d4++) {
            float4 hv = Hrow4[d4];
            QH_STEP(hv.x, 4 * d4 + 0);
            QH_STEP(hv.y, 4 * d4 + 1);
            QH_STEP(hv.z, 4 * d4 + 2);
            QH_STEP(hv.w, 4 * d4 + 3);
        }
    }

    #pragma unroll 1
    for (int o = 0; o < OO; o++) {
        const float* cur = buf + (o & 1) * PER_BO;

        // prefetch next o's params (register-free via cp.async)
        if (o < OO - 1) {
            const float* src = g_scratch + (size_t)(b * OO + o + 1) * PER_BO;
            uint32_t nb = (uint32_t)__cvta_generic_to_shared(buf + ((o + 1) & 1) * PER_BO);
            for (int i = t; i < PER_BO / 4; i += THREADS)
                cp_async16(nb + (uint32_t)i * 16, src + i * 4);
            cp_async_commit();
        }

        // ---- logits ----
        const float* keyb = cur + KEY_OFF;
        const float* cmbb = cur + CMB_OFF;
        float lg[MM];
        #pragma unroll
        for (int m = 0; m < MM; m++) {
            float2 acc = make_float2(0.f, 0.f);
            const float2* kr = (const float2*)(keyb + m * AA + a0);
            #pragma unroll
            for (int j = 0; j < 8; j++) acc = ffma2(qh2[j], kr[j], acc);
            float p = acc.x + acc.y;
            p += __shfl_xor_sync(0xffffffffu, p, 1);   // pair combine -> full row dot
            lg[m] = (p + cmbb[m]) * SCALE;
        }
        // ---- softmax (full row in both pair threads' registers) ----
        float mx = lg[0];
        #pragma unroll
        for (int m = 1; m < MM; m++) mx = fmaxf(mx, lg[m]);
        float sum = 0.f;
        #pragma unroll
        for (int m = 0; m < MM; m++) { lg[m] = __expf(lg[m] - mx); sum += lg[m]; }
        float inv = 1.f / sum;
        #pragma unroll
        for (int m = 0; m < MM; m++) lg[m] *= inv;

        const size_t bo = (size_t)(b * OO + o);

        // ---- attn: direct coalesced float4 stores ----
        {
            float* ao = out + ATTN_OUT_OFF + (bo * NN + n0 + r) * MM;
            if (h == 0) {
                *(float4*)(ao + 0) = make_float4(lg[0], lg[1], lg[2], lg[3]);
                *(float4*)(ao + 4) = make_float4(lg[4], lg[5], lg[6], lg[7]);
            } else {
                *(float4*)(ao + 8) = make_float4(lg[8], lg[9], lg[10], lg[11]);
            }
        }

        // ---- delta + H_time: thread owns (row r, d-half h), 32 d's, 2 chunks ----
        {
            const float* vg   = cur + VALG_OFF + h * 32;
            const float* hsrc = Hrow + h * 32;           // L1-resident
            float* ho = out + (bo * NN + n0 + r) * DD + h * 32;
            #pragma unroll
            for (int c = 0; c < 2; c++) {
                float2 acc[8];
                #pragma unroll
                for (int j = 0; j < 8; j++) acc[j] = make_float2(0.f, 0.f);
                #pragma unroll
                for (int m = 0; m < MM; m++) {
                    const float4* v4 = (const float4*)(vg + m * DD + c * 16);
                    float2 am = make_float2(lg[m], lg[m]);
                    #pragma unroll
                    for (int j = 0; j < 4; j++) {
                        float4 v = v4[j];
                        acc[2 * j + 0] = ffma2(am, make_float2(v.x, v.y), acc[2 * j + 0]);
                        acc[2 * j + 1] = ffma2(am, make_float2(v.z, v.w), acc[2 * j + 1]);
                    }
                }
                const float4* h4 = (const float4*)(hsrc + c * 16);
                float4* o4 = (float4*)(ho + c * 16);
                float2 alpha = make_float2(0.1f, 0.1f);
                #pragma unroll
                for (int j = 0; j < 4; j++) {
                    float4 hv = h4[j];
                    float2 r0 = ffma2(alpha, acc[2 * j + 0], make_float2(hv.x, hv.y));
                    float2 r1 = ffma2(alpha, acc[2 * j + 1], make_float2(hv.z, hv.w));
                    o4[j] = make_float4(r0.x, r0.y, r1.x, r1.y);
                }
            }
        }

        if (o < OO - 1) {
            cp_async_wait_all();
            __syncthreads();   // next buffer staged; cur reads done before overwrite
        }
    }
}

extern "C" void kernel_launch(void* const* d_in, const int* in_sizes, int n_in,
                              void* d_out, int out_size)
{
    const float* H        = (const float*)d_in[0];
    const float* ts_out   = (const float*)d_in[1];
    const float* step_emb = (const float*)d_in[2];
    const float* key_emb  = (const float*)d_in[3];
    const float* val_emb  = (const float*)d_in[4];
    const float* Wk       = (const float*)d_in[5];
    const float* Wg       = (const float*)d_in[6];
    const float* bg       = (const float*)d_in[7];
    const float* Wq       = (const float*)d_in[8];
    const float* bq       = (const float*)d_in[9];
    float* out = (float*)d_out;

    precompute_kernel<<<BB * OO, 64>>>(ts_out, step_emb, key_emb, val_emb,
                                       Wk, Wg, bg, Wq, bq, out);
    dim3 grid(NN / TILE_N, BB);
    stta_main<<<grid, THREADS>>>(H, Wq, out);
}

// round 3
// speedup vs baseline: 2.0729x; 2.0729x over previous
#include <cuda_runtime.h>
#include <math.h>
#include <stdint.h>

// Problem constants
#define BB 16
#define NN 4096
#define DD 64
#define OO 12
#define SS 32
#define MM 12
#define AA 32

#define TILE_N 128
#define THREADS 256

#define SCALE 0.17677669529663687f   // 1/sqrt(32)
#define TWO_PI 6.283185307179586f

// Scratch per (b,o): sn[12+4] | cs[12+4] | cmb_scaled[12+4] | valg[12][64]
#define SN_OFF   0
#define CS_OFF   16
#define CMB_OFF  32
#define VALG_OFF 48
#define PER_BO   816        // floats, 16B aligned

__device__ float g_scratch[BB * OO * PER_BO];

#define ATTN_OUT_OFF ((size_t)BB*OO*NN*DD)
#define GATE_OUT_OFF (ATTN_OUT_OFF + (size_t)BB*OO*NN*MM)

// Shared layout (floats)
#define WQT_STRIDE 34
#define AT_STRIDE  132
#define SM_WQT 0
#define SM_KE  (SM_WQT + DD*WQT_STRIDE)   // 2176
#define SM_WK0 (SM_KE + MM*AA)            // 2560
#define SM_WK1 (SM_WK0 + 32)              // 2592
#define SM_AT  (SM_WK1 + 32)              // 2624
#define SM_BUF (SM_AT + MM*AT_STRIDE)     // 4208
#define SMEM_FLOATS (SM_BUF + 2*PER_BO)   // 5840 floats = 23360 B

// Packed dual-FMA (fp32x2) — ptxas never auto-fuses this.
__device__ __forceinline__ float2 ffma2(float2 a, float2 b, float2 c) {
    float2 d;
    asm("{\n"
        ".reg .b64 ra, rb, rc, rd;\n"
        "mov.b64 ra, {%2, %3};\n"
        "mov.b64 rb, {%4, %5};\n"
        "mov.b64 rc, {%6, %7};\n"
        "fma.rn.f32x2 rd, ra, rb, rc;\n"
        "mov.b64 {%0, %1}, rd;\n"
        "}"
        : "=f"(d.x), "=f"(d.y)
        : "f"(a.x), "f"(a.y), "f"(b.x), "f"(b.y), "f"(c.x), "f"(c.y));
    return d;
}

__device__ __forceinline__ void cp_async16(uint32_t dst_smem, const void* src) {
    asm volatile("cp.async.cg.shared.global [%0], [%1], 16;\n" :: "r"(dst_smem), "l"(src));
}
__device__ __forceinline__ void cp_async_commit() { asm volatile("cp.async.commit_group;\n"); }
__device__ __forceinline__ void cp_async_wait_all() { asm volatile("cp.async.wait_group 0;\n" ::: "memory"); }

// ---------------------------------------------------------------------------
// Precompute per-(b,o): sn, cs, cmb*SCALE, gate*val_emb, gate output.
// ---------------------------------------------------------------------------
__global__ void precompute_kernel(const float* __restrict__ ts_out,
                                  const float* __restrict__ step_emb,
                                  const float* __restrict__ key_emb,
                                  const float* __restrict__ val_emb,
                                  const float* __restrict__ Wk,
                                  const float* __restrict__ Wg,
                                  const float* __restrict__ bg,
                                  const float* __restrict__ Wq,
                                  const float* __restrict__ bq,
                                  float* __restrict__ out)
{
    __shared__ float qs_s[AA];
    __shared__ float key_sh[MM * AA];
    __shared__ float gate_sh[MM];

    const int bo = blockIdx.x;
    const int t  = threadIdx.x;
    const float tod = ts_out[bo * 2 + 0];
    const float dow = ts_out[bo * 2 + 1];
    float* dst = g_scratch + (size_t)bo * PER_BO;

    // key[m][a] into shared (for cmb)
    for (int i = t; i < MM * AA; i += 64) {
        int m = i >> 5, a = i & 31;
        float ph = (m < 8) ? tod : dow;
        float kf = (m < 8) ? (float)(m + 1) : (float)(m - 7);
        float sn, cs; sincosf(TWO_PI * ph * kf, &sn, &cs);
        key_sh[i] = sn * Wk[a * 2 + 0] + cs * Wk[a * 2 + 1] + key_emb[i];
    }
    if (t < MM) {
        int m = t;
        float ph = (m < 8) ? tod : dow;
        float kf = (m < 8) ? (float)(m + 1) : (float)(m - 7);
        float sn, cs; sincosf(TWO_PI * ph * kf, &sn, &cs);
        dst[SN_OFF + m] = sn;
        dst[CS_OFF + m] = cs;
        float gv = tanhf(sn * Wg[0] + cs * Wg[1] + bg[0]);
        gate_sh[m] = gv;
        out[GATE_OUT_OFF + (size_t)bo * MM + m] = gv;
    } else if (t < 16) {
        dst[SN_OFF + t] = 0.f; dst[CS_OFF + t] = 0.f; dst[CMB_OFF + t] = 0.f;
    }
    if (t < AA) {
        float acc = bq[t];
        const float* se = step_emb + bo * SS;
        const float* wr = Wq + t * (DD + SS) + DD;
        #pragma unroll 8
        for (int si = 0; si < SS; si++) acc = fmaf(se[si], wr[si], acc);
        qs_s[t] = acc;
    }
    __syncthreads();
    for (int i = t; i < MM * DD; i += 64) {
        int m = i >> 6;
        dst[VALG_OFF + i] = gate_sh[m] * val_emb[i];
    }
    if (t < MM) {
        float acc = 0.f;
        #pragma unroll
        for (int a = 0; a < AA; a++) acc += qs_s[a] * key_sh[t * AA + a];
        dst[CMB_OFF + t] = acc * SCALE;
    }
}

// ---------------------------------------------------------------------------
// Main kernel: block = (b, 128-row tile), loops over O.
// ---------------------------------------------------------------------------
__global__ __launch_bounds__(THREADS, 4)
void stta_main(const float* __restrict__ H, const float* __restrict__ Wq,
               const float* __restrict__ key_emb, const float* __restrict__ Wk,
               float* __restrict__ out)
{
    __shared__ float s[SMEM_FLOATS];
    float* wqt = s + SM_WQT;
    float* ke  = s + SM_KE;
    float* wk0 = s + SM_WK0;
    float* wk1 = s + SM_WK1;
    float* at  = s + SM_AT;
    float* buf = s + SM_BUF;

    const int t  = threadIdx.x;
    const int b  = blockIdx.y;
    const int n0 = blockIdx.x * TILE_N;

    // prefetch o=0 params
    {
        const float* src = g_scratch + (size_t)(b * OO) * PER_BO;
        uint32_t nb = (uint32_t)__cvta_generic_to_shared(buf);
        for (int i = t; i < PER_BO / 4; i += THREADS)
            cp_async16(nb + (uint32_t)i * 16, src + i * 4);
        cp_async_commit();
    }
    // stage Wqt, key_emb, Wk columns
    for (int i = t; i < AA * DD; i += THREADS) {
        int a = i >> 6, d = i & 63;
        wqt[d * WQT_STRIDE + a] = Wq[a * (DD + SS) + d];
    }
    for (int i = t; i < MM * AA; i += THREADS) ke[i] = key_emb[i];
    if (t < 32) { wk0[t] = Wk[t * 2]; wk1[t] = Wk[t * 2 + 1]; }
    cp_async_wait_all();
    __syncthreads();

    const int r  = t >> 1;
    const int h  = t & 1;
    const int a0 = h * 16;

    // qh (transient) -> es[12], p0s, p1s (persistent, pre-scaled)
    float es[MM];
    float p0s, p1s;
    {
        const float* Hrow = H + ((size_t)b * NN + n0 + r) * DD;
        float2 qh2[8];
        #pragma unroll
        for (int j = 0; j < 8; j++) qh2[j] = make_float2(0.f, 0.f);
        const float4* Hrow4 = (const float4*)Hrow;
        #pragma unroll 4
        for (int d4 = 0; d4 < 16; d4++) {
            float4 hv = Hrow4[d4];
            #pragma unroll
            for (int q = 0; q < 4; q++) {
                float hvq = (q == 0) ? hv.x : (q == 1) ? hv.y : (q == 2) ? hv.z : hv.w;
                float2 hd = make_float2(hvq, hvq);
                const float* wrow = wqt + (4 * d4 + q) * WQT_STRIDE + a0;
                #pragma unroll
                for (int j = 0; j < 8; j++)
                    qh2[j] = ffma2(hd, *(const float2*)(wrow + 2 * j), qh2[j]);
            }
        }
        #pragma unroll
        for (int m = 0; m < MM; m++) {
            float2 acc = make_float2(0.f, 0.f);
            const float* kr = ke + m * AA + a0;
            #pragma unroll
            for (int j = 0; j < 8; j++)
                acc = ffma2(qh2[j], *(const float2*)(kr + 2 * j), acc);
            float p = acc.x + acc.y;
            p += __shfl_xor_sync(0xffffffffu, p, 1);
            es[m] = p * SCALE;
        }
        float2 a0v = make_float2(0.f, 0.f), a1v = make_float2(0.f, 0.f);
        #pragma unroll
        for (int j = 0; j < 8; j++) {
            a0v = ffma2(qh2[j], *(const float2*)(wk0 + a0 + 2 * j), a0v);
            a1v = ffma2(qh2[j], *(const float2*)(wk1 + a0 + 2 * j), a1v);
        }
        float p0 = a0v.x + a0v.y; p0 += __shfl_xor_sync(0xffffffffu, p0, 1);
        float p1 = a1v.x + a1v.y; p1 += __shfl_xor_sync(0xffffffffu, p1, 1);
        p0s = p0 * SCALE; p1s = p1 * SCALE;
    }

    const int dp = t & 31;          // d-pair index: d = 2*dp
    const int g  = t >> 5;          // row group (8 groups x 16 rows)
    const float* h2src = H + ((size_t)b * NN + n0 + g * 16) * DD + 2 * dp;

    #pragma unroll 1
    for (int o = 0; o < OO; o++) {
        const float* cur = buf + (o & 1) * PER_BO;
        if (o < OO - 1) {
            const float* src = g_scratch + (size_t)(b * OO + o + 1) * PER_BO;
            uint32_t nb = (uint32_t)__cvta_generic_to_shared(buf + ((o + 1) & 1) * PER_BO);
            for (int i = t; i < PER_BO / 4; i += THREADS)
                cp_async16(nb + (uint32_t)i * 16, src + i * 4);
            cp_async_commit();
        }

        // ---- P1: logits (2 fma per m) + softmax ----
        float snv[MM], csv[MM], cmbv[MM];
        {
            const float4* c4 = (const float4*)cur;
            #pragma unroll
            for (int j = 0; j < 3; j++) {
                ((float4*)snv)[j]  = c4[SN_OFF / 4 + j];
                ((float4*)csv)[j]  = c4[CS_OFF / 4 + j];
                ((float4*)cmbv)[j] = c4[CMB_OFF / 4 + j];
            }
        }
        float lg[MM];
        #pragma unroll
        for (int m = 0; m < MM; m++)
            lg[m] = fmaf(snv[m], p0s, fmaf(csv[m], p1s, es[m] + cmbv[m]));

        float mx = lg[0];
        #pragma unroll
        for (int m = 1; m < MM; m++) mx = fmaxf(mx, lg[m]);
        float sum = 0.f;
        #pragma unroll
        for (int m = 0; m < MM; m++) { lg[m] = __expf(lg[m] - mx); sum += lg[m]; }
        float inv = 1.f / sum;
        #pragma unroll
        for (int m = 0; m < MM; m++) lg[m] *= inv;

        const size_t bo = (size_t)(b * OO + o);
        // attn global stores (coalesced float4)
        {
            float* ao = out + ATTN_OUT_OFF + (bo * NN + n0 + r) * MM;
            if (h == 0) {
                *(float4*)(ao + 0) = make_float4(lg[0], lg[1], lg[2], lg[3]);
                *(float4*)(ao + 4) = make_float4(lg[4], lg[5], lg[6], lg[7]);
            } else {
                *(float4*)(ao + 8) = make_float4(lg[8], lg[9], lg[10], lg[11]);
            }
        }
        // attn transposed to shared for delta
        #pragma unroll
        for (int j = 0; j < 6; j++)
            at[(6 * h + j) * AT_STRIDE + r] = lg[6 * h + j];
        __syncthreads();

        // ---- P2: delta + H_time. Thread owns d-pair dp, 16 rows ----
        {
            float2 vg[MM];
            #pragma unroll
            for (int m = 0; m < MM; m++)
                vg[m] = *(const float2*)(cur + VALG_OFF + m * DD + 2 * dp);

            float* ho = out + (bo * NN + n0 + g * 16) * DD + 2 * dp;
            const float2 alpha = make_float2(0.1f, 0.1f);
            #pragma unroll
            for (int c = 0; c < 4; c++) {
                const int rr = g * 16 + c * 4;
                float2 acc0 = make_float2(0.f, 0.f), acc1 = acc0, acc2 = acc0, acc3 = acc0;
                #pragma unroll
                for (int m = 0; m < MM; m++) {
                    float4 a4 = *(const float4*)(at + m * AT_STRIDE + rr);  // warp broadcast
                    acc0 = ffma2(make_float2(a4.x, a4.x), vg[m], acc0);
                    acc1 = ffma2(make_float2(a4.y, a4.y), vg[m], acc1);
                    acc2 = ffma2(make_float2(a4.z, a4.z), vg[m], acc2);
                    acc3 = ffma2(make_float2(a4.w, a4.w), vg[m], acc3);
                }
                #pragma unroll
                for (int i = 0; i < 4; i++) {
                    float2 acc = (i == 0) ? acc0 : (i == 1) ? acc1 : (i == 2) ? acc2 : acc3;
                    float2 hv = *(const float2*)(h2src + (size_t)(c * 4 + i) * DD);
                    float2 res = ffma2(alpha, acc, hv);
                    *(float2*)(ho + (size_t)(c * 4 + i) * DD) = res;
                }
            }
        }

        cp_async_wait_all();
        __syncthreads();
    }
}

extern "C" void kernel_launch(void* const* d_in, const int* in_sizes, int n_in,
                              void* d_out, int out_size)
{
    const float* H        = (const float*)d_in[0];
    const float* ts_out   = (const float*)d_in[1];
    const float* step_emb = (const float*)d_in[2];
    const float* key_emb  = (const float*)d_in[3];
    const float* val_emb  = (const float*)d_in[4];
    const float* Wk       = (const float*)d_in[5];
    const float* Wg       = (const float*)d_in[6];
    const float* bg       = (const float*)d_in[7];
    const float* Wq       = (const float*)d_in[8];
    const float* bq       = (const float*)d_in[9];
    float* out = (float*)d_out;

    precompute_kernel<<<BB * OO, 64>>>(ts_out, step_emb, key_emb, val_emb,
                                       Wk, Wg, bg, Wq, bq, out);
    dim3 grid(NN / TILE_N, BB);
    stta_main<<<grid, THREADS>>>(H, Wq, key_emb, Wk, out);
}